// round 16
// baseline (speedup 1.0000x reference)
#include <cuda_runtime.h>

constexpr int B_ = 8192;
constexpr int K_ = 32;
constexpr int D_ = 129;
constexpr int V_ = 2048;
constexpr int KTOP = 10;
constexpr float WEIGHT_ = 0.15f;

constexpr int NS = B_ / 2;        // 4096 streaming blocks (2 rows each)
constexpr int NE = B_ / 8;        // 1024 epilogue blocks (8 rows each)
constexpr int NCHUNK = 128;       // 64 rows per chunk

__device__ float g_d[B_ * 33];
__device__ int   g_flag[B_];
__device__ float g_loss[B_];
__device__ float g_chunk[NCHUNK];
__device__ int   g_chunkcnt[NCHUNK];
__device__ int   g_ccnt;

__device__ __forceinline__ float warp_sum(float v) {
#pragma unroll
    for (int o = 16; o; o >>= 1) v += __shfl_xor_sync(0xffffffffu, v, o);
    return v;
}
__device__ __forceinline__ float warp_max(float v) {
#pragma unroll
    for (int o = 16; o; o >>= 1) v = fmaxf(v, __shfl_xor_sync(0xffffffffu, v, o));
    return v;
}
__device__ __forceinline__ float acoshd(float x) {
    x = fmaxf(x, 1.0f + 1e-7f);
    return __logf(x + sqrtf(fmaf(x, x, -1.0f)));
}
__device__ __forceinline__ float inv_log2(float n) {
    return __fdividef(1.0f, __log2f(n));
}
__device__ __forceinline__ float pair_term(float ri, float ci, float di,
                                           float rj, float cj, float dj,
                                           float inv_idcg) {
    float drel  = ri - rj;
    float delta = fabsf(drel * (ci - cj)) * inv_idcg;
    float dd    = dj - di;
    float s     = (drel > 0.0f) ? 1.0f : -1.0f;
    float x     = s * dd;
    float sig   = __fdividef(1.0f, 1.0f + __expf(-x));
    return s * delta * sig * (-dd);
}

// 8-item tile: fold 32->8 lanes, transpose-reduce; returns total of item
// (lane & 7), replicated across the four octets. (verified exact R5/R11/R12)
__device__ __forceinline__ float tile_reduce8(float q[8], int lane) {
#pragma unroll
    for (int k = 0; k < 8; k++) {
        q[k] += __shfl_xor_sync(0xffffffffu, q[k], 16);
        q[k] += __shfl_xor_sync(0xffffffffu, q[k], 8);
    }
    const int ll = lane & 7;
#pragma unroll
    for (int m = 4; m >= 1; m >>= 1) {
        const bool up = (ll & m) != 0;
#pragma unroll
        for (int t = 0; t < m; t++) {
            float send = up ? q[t] : q[t + m];
            float recv = __shfl_xor_sync(0xffffffffu, send, m);
            q[t] = (up ? q[t + m] : q[t]) + recv;
        }
    }
    return q[0];
}

__global__ void __launch_bounds__(256, 5) lr_split(
    const float* __restrict__ anchor,
    const float* __restrict__ positive,
    const float* __restrict__ negative,
    const float* __restrict__ tree,
    const int*   __restrict__ aidx,
    const int*   __restrict__ pidx,
    const int*   __restrict__ nidx,
    float*       __restrict__ out)
{
    const int w    = threadIdx.x >> 5;
    const int lane = threadIdx.x & 31;

    if (blockIdx.x < NS) {
        // ================= streaming block: R12 phase-1 shape =================
        const int ll = lane & 7;
        const int r  = w >> 2;              // local row 0/1
        const int g  = w & 3;               // item group
        const int b  = blockIdx.x * 2 + r;

        const float* __restrict__ arow = anchor   + (size_t)b * D_;
        const float* __restrict__ pb   = positive + (size_t)b * D_;
        const float* __restrict__ nb   = negative + (size_t)b * K_ * D_;

        const float ah0 = (lane == 0) ? arow[0] : -arow[lane];
        const float ah1 = -arow[lane + 32];
        const float ah2 = -arow[lane + 64];
        const float ah3 = -arow[lane + 96];
        const float a128n = -arow[128];

        float q[8];
#pragma unroll
        for (int k = 0; k < 8; k++) {
            const int t = 8 * g + k;
            const float* v = (t == 0) ? pb : (nb + (t - 1) * D_);
            q[k] = fmaf(ah0, __ldcs(v + lane), fmaf(ah1, __ldcs(v + lane + 32),
                   fmaf(ah2, __ldcs(v + lane + 64), ah3 * __ldcs(v + lane + 96))));
        }
        float p32 = 0.0f, e32 = 0.0f;
        if (g == 3) {
            const float* v = nb + 31 * D_;
            p32 = fmaf(ah0, __ldcs(v + lane), fmaf(ah1, __ldcs(v + lane + 32),
                  fmaf(ah2, __ldcs(v + lane + 64), ah3 * __ldcs(v + lane + 96))));
            e32 = __ldcs(v + 128);
        }
        const int tl = 8 * g + ll;
        const float e128 = __ldcs(((tl == 0) ? pb : (nb + (tl - 1) * D_)) + 128);

        const float dsum = tile_reduce8(q, lane) + a128n * e128;
        const float dval = acoshd(dsum);
        if (lane < 8) __stcg(g_d + b * 33 + 8 * g + lane, dval);
        if (g == 3) {
            const float s32 = warp_sum(p32) + a128n * e32;
            if (lane == 0) __stcg(g_d + b * 33 + 32, acoshd(s32));
        }
        __syncthreads();                     // both rows' d complete in this block
        if (threadIdx.x == 0) {              // one fence + 2 flag stores per block
            __threadfence();
            __stcg(g_flag + blockIdx.x * 2,     1);
            __stcg(g_flag + blockIdx.x * 2 + 1, 1);
        }
        return;
    }

    // ================= epilogue block: one warp per row =================
    const int b = (blockIdx.x - NS) * 8 + w;

    // gather chain issued before the spin (independent of d)
    const int ai    = __ldg(aidx + b);
    const int colme = (lane == 0) ? __ldg(pidx + b) : __ldg(nidx + b * K_ + lane - 1);
    const int col32 = __ldg(nidx + b * K_ + 31);
    const float* __restrict__ trow = tree + (size_t)ai * V_;
    const float tme = __ldg(trow + colme);
    const float t32 = __ldg(trow + col32);

    // spin (lane 0) with backoff until this row's distances are published
    if (lane == 0) {
        while (((volatile int*)g_flag)[b] == 0) __nanosleep(300);
        g_flag[b] = 0;                       // self-reset for graph replay
    }
    __syncwarp();
    __threadfence();                         // pair with producer fence

    const float dme = __ldcg(g_d + b * 33 + lane);
    const float d32 = __ldcg(g_d + b * 33 + 32);

    const float maxt   = fmaxf(warp_max(tme), t32);
    const float inv_mt = __fdividef(1.0f, maxt + 1e-6f);
    const float relme  = (maxt - tme + 1e-6f) * inv_mt;
    const float rel32  = (maxt - t32 + 1e-6f) * inv_mt;

    int rank = 1, rr = 0;
#pragma unroll
    for (int o = 1; o < 32; o++) {
        const int j = (lane + o) & 31;
        const float dj = __shfl_sync(0xffffffffu, dme,   j);
        const float rj = __shfl_sync(0xffffffffu, relme, j);
        rank += (dj < dme)   || (dj == dme   && j < lane);
        rr   += (rj > relme) || (rj == relme && j < lane);
    }
    rank += (d32 < dme);
    rr   += (rel32 > relme);

    const int rank32 = 1 + (int)__reduce_add_sync(0xffffffffu, (unsigned)(dme <= d32));
    const int rr32   =     (int)__reduce_add_sync(0xffffffffu, (unsigned)(relme >= rel32));

    const float cme = (rank   <= KTOP) ? inv_log2((float)(rank   + 1)) : 0.0f;
    const float c32 = (rank32 <= KTOP) ? inv_log2((float)(rank32 + 1)) : 0.0f;

    float ic = (rr < KTOP) ? relme * inv_log2((float)(rr + 2)) : 0.0f;
    if (lane == 0 && rr32 < KTOP) ic += rel32 * inv_log2((float)(rr32 + 2));
    const float idcg = warp_sum(ic);
    const float inv_idcg = (idcg > 0.0f) ? __fdividef(1.0f, idcg) : 0.0f;

    float acc = 0.0f;
#pragma unroll
    for (int o = 1; o <= 16; o++) {
        const int j = (lane + o) & 31;
        const float rj = __shfl_sync(0xffffffffu, relme, j);
        const float cj = __shfl_sync(0xffffffffu, cme,   j);
        const float dj = __shfl_sync(0xffffffffu, dme,   j);
        const float t  = pair_term(relme, cme, dme, rj, cj, dj, inv_idcg);
        acc += (o == 16) ? 0.5f * t : t;
    }
    acc += pair_term(relme, cme, dme, rel32, c32, d32, inv_idcg);
    acc = warp_sum(acc);

    // fenced completion tree (64 rows/chunk -> 128 chunks), proven in R15
    if (lane == 0) __stcg(g_loss + b, acc);
    __threadfence();

    const int c = b >> 6;
    int pc = 0;
    if (lane == 0) pc = atomicAdd(&g_chunkcnt[c], 1);
    pc = __shfl_sync(0xffffffffu, pc, 0);
    if (pc == 63) {
        if (lane == 0) g_chunkcnt[c] = 0;    // self-reset
        __threadfence();
        const int base = c * 64;
        float v = __ldcg(g_loss + base + lane) + __ldcg(g_loss + base + 32 + lane);
        v = warp_sum(v);
        if (lane == 0) __stcg(g_chunk + c, v);
        __threadfence();
        int pf = 0;
        if (lane == 0) pf = atomicAdd(&g_ccnt, 1);
        pf = __shfl_sync(0xffffffffu, pf, 0);
        if (pf == NCHUNK - 1) {
            if (lane == 0) g_ccnt = 0;       // self-reset
            __threadfence();
            float s = 0.0f;
#pragma unroll
            for (int t = 0; t < 4; t++) s += __ldcg(g_chunk + t * 32 + lane);
            s = warp_sum(s);
            if (lane == 0) out[0] = WEIGHT_ * s / (float)B_;
        }
    }
}

extern "C" void kernel_launch(void* const* d_in, const int* in_sizes, int n_in,
                              void* d_out, int out_size)
{
    const float* anchor   = (const float*)d_in[0];
    const float* positive = (const float*)d_in[1];
    const float* negative = (const float*)d_in[2];
    const float* tree     = (const float*)d_in[3];
    const int*   aidx     = (const int*)d_in[4];
    const int*   pidx     = (const int*)d_in[5];
    const int*   nidx     = (const int*)d_in[6];

    lr_split<<<NS + NE, 256>>>(anchor, positive, negative, tree,
                               aidx, pidx, nidx, (float*)d_out);
}